// round 12
// baseline (speedup 1.0000x reference)
#include <cuda_runtime.h>
#include <cuda_bf16.h>

// GraphSAGE inference — algebraic reduction + warp-per-row gather, occupancy-max.
//   agg0[b] = (mean_n [e_n | mean_nn e_nn]) @ W1   (fc1 linear => commutes with mean)
// 128-thread blocks (4 warps = 4 batch rows), <=51 regs -> 10 CTAs/SM = 40 warps.
// Shapes fixed: B=4096, N0=10, N1=25, D=64, H=128.

#define B_     4096
#define N0_    10
#define N1_    25
#define D_     64
#define GB     4            // batch rows per block = warps per block
#define NBLK   (B_ / GB)    // 1024 blocks
#define SNW    264          // ints per warp id buffer (250 n1 + 10 n0, padded)

// Weights packed (k4, j) as ulonglong2 of packed-f32x2 K values.
__device__ ulonglong2 g_W1q[32 * 128];   // K=128
__device__ ulonglong2 g_W0q[48 * 128];   // K=192

// ---- packed-fp32 helpers (f32x2 only via PTX) ----
__device__ __forceinline__ unsigned long long pack2(float a, float b) {
    unsigned long long r;
    asm("mov.b64 %0, {%1, %2};" : "=l"(r) : "f"(a), "f"(b));
    return r;
}
__device__ __forceinline__ void unpack2(unsigned long long v, float& a, float& b) {
    asm("mov.b64 {%0, %1}, %2;" : "=f"(a), "=f"(b) : "l"(v));
}
__device__ __forceinline__ void ffma2(unsigned long long& d,
                                      unsigned long long a, unsigned long long b) {
    asm("fma.rn.f32x2 %0, %1, %2, %0;" : "+l"(d) : "l"(a), "l"(b));
}

__global__ void prep_w(const float* __restrict__ W1, const float* __restrict__ W0) {
    const int j = threadIdx.x;
    if (blockIdx.x < 32) {
        const int k4 = blockIdx.x;
        ulonglong2 v;
        v.x = pack2(W1[(4 * k4 + 0) * 128 + j], W1[(4 * k4 + 1) * 128 + j]);
        v.y = pack2(W1[(4 * k4 + 2) * 128 + j], W1[(4 * k4 + 3) * 128 + j]);
        g_W1q[k4 * 128 + j] = v;
    } else {
        const int k4 = blockIdx.x - 32;
        ulonglong2 v;
        v.x = pack2(W0[(4 * k4 + 0) * 128 + j], W0[(4 * k4 + 1) * 128 + j]);
        v.y = pack2(W0[(4 * k4 + 2) * 128 + j], W0[(4 * k4 + 3) * 128 + j]);
        g_W0q[k4 * 128 + j] = v;
    }
}

__global__ void __launch_bounds__(128, 10) sage_v4(
    const int*   __restrict__ inputs,
    const int*   __restrict__ neigh0,
    const int*   __restrict__ neigh1,
    const float* __restrict__ embed,
    const float* __restrict__ b0,
    float*       __restrict__ out)
{
    __shared__ int snbuf[GB * SNW];                  // per-warp id staging
    __shared__ __align__(16) float xbar[GB][128];    // [sum(e_n)/10 | sum(e_nn)/250]
    __shared__ __align__(16) float xb[GB][192];      // [e_v | agg0]

    const int t    = threadIdx.x;                    // 0..127
    const int w    = t >> 5;                         // warp = local batch row
    const int lane = t & 31;
    const int c4   = lane & 15;                      // float4 column slot
    const int hh   = lane >> 4;                      // even/odd id half
    const int row  = blockIdx.x * GB + w;            // global batch row
    const float4* eb = (const float4*)embed;
    int* sn = &snbuf[w * SNW];

    // ---- stage this warp's ids (warp-private) ----
    for (int i = lane; i < N0_ * N1_; i += 32)
        sn[i] = __ldg(neigh1 + (size_t)row * (N0_ * N1_) + i);
    if (lane < N0_)
        sn[250 + lane] = __ldg(neigh0 + row * N0_ + lane);
    __syncwarp();

    // ---- gather-sum: half hh sums ids hh, hh+2, ... (125 of 250) ----
    float4 a1 = make_float4(0.f, 0.f, 0.f, 0.f);
    {
        const int* sni = sn + hh;
        #pragma unroll 1
        for (int it = 0; it < 25; it++) {            // 25 batches x 5 loads
            const int base = it * 10;
            const float4 v0 = __ldg(eb + (size_t)sni[base + 0] * 16 + c4);
            const float4 v1 = __ldg(eb + (size_t)sni[base + 2] * 16 + c4);
            const float4 v2 = __ldg(eb + (size_t)sni[base + 4] * 16 + c4);
            const float4 v3 = __ldg(eb + (size_t)sni[base + 6] * 16 + c4);
            const float4 v4 = __ldg(eb + (size_t)sni[base + 8] * 16 + c4);
            a1.x += v0.x + v1.x + v2.x + v3.x + v4.x;
            a1.y += v0.y + v1.y + v2.y + v3.y + v4.y;
            a1.z += v0.z + v1.z + v2.z + v3.z + v4.z;
            a1.w += v0.w + v1.w + v2.w + v3.w + v4.w;
        }
    }
    // neigh0: 5 ids per half
    float4 a0;
    {
        const int* sn0 = sn + 250 + hh;
        const float4 u0 = __ldg(eb + (size_t)sn0[0] * 16 + c4);
        const float4 u1 = __ldg(eb + (size_t)sn0[2] * 16 + c4);
        const float4 u2 = __ldg(eb + (size_t)sn0[4] * 16 + c4);
        const float4 u3 = __ldg(eb + (size_t)sn0[6] * 16 + c4);
        const float4 u4 = __ldg(eb + (size_t)sn0[8] * 16 + c4);
        a0 = make_float4(u0.x + u1.x + u2.x + u3.x + u4.x,
                         u0.y + u1.y + u2.y + u3.y + u4.y,
                         u0.z + u1.z + u2.z + u3.z + u4.z,
                         u0.w + u1.w + u2.w + u3.w + u4.w);
    }
    // e_v row (upper half loads it while lower half reduces)
    float4 ev = make_float4(0.f, 0.f, 0.f, 0.f);
    if (hh == 1)
        ev = __ldg(eb + (size_t)__ldg(inputs + row) * 16 + c4);

    // ---- combine halves via shfl.xor 16 (warp-local) ----
    a1.x += __shfl_xor_sync(0xffffffffu, a1.x, 16);
    a1.y += __shfl_xor_sync(0xffffffffu, a1.y, 16);
    a1.z += __shfl_xor_sync(0xffffffffu, a1.z, 16);
    a1.w += __shfl_xor_sync(0xffffffffu, a1.w, 16);
    a0.x += __shfl_xor_sync(0xffffffffu, a0.x, 16);
    a0.y += __shfl_xor_sync(0xffffffffu, a0.y, 16);
    a0.z += __shfl_xor_sync(0xffffffffu, a0.z, 16);
    a0.w += __shfl_xor_sync(0xffffffffu, a0.w, 16);

    if (hh == 0) {
        const float s1 = 1.f / 250.f, s0 = 1.f / 10.f;
        *(float4*)&xbar[w][64 + 4 * c4] =
            make_float4(a1.x * s1, a1.y * s1, a1.z * s1, a1.w * s1);
        *(float4*)&xbar[w][4 * c4] =
            make_float4(a0.x * s0, a0.y * s0, a0.z * s0, a0.w * s0);
    } else {
        *(float4*)&xb[w][4 * c4] = ev;
    }
    __syncthreads();                                 // only block barrier pre-fc

    const int j = t;                                 // 0..127 output column

    // ---- fc1: agg0[r] = xbar[r] @ W1 (all 4 rows per thread) ----
    {
        unsigned long long acc[GB] = {0ull, 0ull, 0ull, 0ull};
        #pragma unroll 4
        for (int k4 = 0; k4 < 32; k4++) {
            const ulonglong2 wv = g_W1q[k4 * 128 + j];
            #pragma unroll
            for (int r = 0; r < GB; r++) {
                const ulonglong2 xv = *(const ulonglong2*)&xbar[r][4 * k4];
                ffma2(acc[r], xv.x, wv.x);
                ffma2(acc[r], xv.y, wv.y);
            }
        }
        #pragma unroll
        for (int r = 0; r < GB; r++) {
            float a, b; unpack2(acc[r], a, b);
            xb[r][64 + j] = a + b;
        }
    }
    __syncthreads();

    // ---- fc0 + sigmoid ----
    {
        unsigned long long acc[GB] = {0ull, 0ull, 0ull, 0ull};
        #pragma unroll 4
        for (int k4 = 0; k4 < 48; k4++) {
            const ulonglong2 wv = g_W0q[k4 * 128 + j];
            #pragma unroll
            for (int r = 0; r < GB; r++) {
                const ulonglong2 xv = *(const ulonglong2*)&xb[r][4 * k4];
                ffma2(acc[r], xv.x, wv.x);
                ffma2(acc[r], xv.y, wv.y);
            }
        }
        const float bj = __ldg(b0 + j);
        const int bb = blockIdx.x * GB;
        #pragma unroll
        for (int r = 0; r < GB; r++) {
            float a, b; unpack2(acc[r], a, b);
            const float hv = a + b + bj;
            out[(size_t)(bb + r) * 128 + j] = 1.f / (1.f + __expf(-hv));
        }
    }
}

extern "C" void kernel_launch(void* const* d_in, const int* in_sizes, int n_in,
                              void* d_out, int out_size)
{
    // Bind inputs by element count (all distinct):
    //   inputs 4096 | neigh0 40960 | neigh1 1024000 | embed 64000064
    //   W1 16384 | W0 24576 | b0 128
    const int *inputs = nullptr, *neigh0 = nullptr, *neigh1 = nullptr;
    const float *embed = nullptr, *W1 = nullptr, *W0 = nullptr, *b0 = nullptr;
    for (int i = 0; i < n_in; i++) {
        switch (in_sizes[i]) {
            case 4096:     inputs = (const int*)  d_in[i]; break;
            case 40960:    neigh0 = (const int*)  d_in[i]; break;
            case 1024000:  neigh1 = (const int*)  d_in[i]; break;
            case 64000064: embed  = (const float*)d_in[i]; break;
            case 16384:    W1     = (const float*)d_in[i]; break;
            case 24576:    W0     = (const float*)d_in[i]; break;
            case 128:      b0     = (const float*)d_in[i]; break;
        }
    }

    prep_w<<<80, 128>>>(W1, W0);
    sage_v4<<<NBLK, 128>>>(inputs, neigh0, neigh1, embed, b0, (float*)d_out);
}

// round 13
// speedup vs baseline: 1.0294x; 1.0294x over previous
#include <cuda_runtime.h>
#include <cuda_bf16.h>

// GraphSAGE inference — algebraic reduction, split kernels.
//   agg0[b] = (mean_n [e_n | mean_nn e_nn]) @ W1  (fc1 linear => commutes w/ mean)
// Kernel A: gather-sum, TWO warps per batch row (8192 warps total) -> xbar (2MB, L2).
// Kernel B: fc1 + fc0 + sigmoid (512 blocks, W L2 traffic stays 82MB).
// Shapes fixed: B=4096, N0=10, N1=25, D=64, H=128.

#define B_     4096
#define N0_    10
#define N1_    25
#define D_     64
#define RPB_A  4            // rows per block in gather kernel (8 warps)
#define GB     8            // rows per block in fc kernel
#define NBLK_A (B_ / RPB_A) // 1024
#define NBLK_B (B_ / GB)    // 512

__device__ float g_xbar[(size_t)B_ * 128];    // [sum(e_n)/10 | sum(e_nn)/250], 2MB

// Weights packed (k4, j) as ulonglong2 of packed-f32x2 K values.
__device__ ulonglong2 g_W1q[32 * 128];   // K=128
__device__ ulonglong2 g_W0q[48 * 128];   // K=192

// ---- packed-fp32 helpers (f32x2 only via PTX) ----
__device__ __forceinline__ unsigned long long pack2(float a, float b) {
    unsigned long long r;
    asm("mov.b64 %0, {%1, %2};" : "=l"(r) : "f"(a), "f"(b));
    return r;
}
__device__ __forceinline__ void unpack2(unsigned long long v, float& a, float& b) {
    asm("mov.b64 {%0, %1}, %2;" : "=f"(a), "=f"(b) : "l"(v));
}
__device__ __forceinline__ void ffma2(unsigned long long& d,
                                      unsigned long long a, unsigned long long b) {
    asm("fma.rn.f32x2 %0, %1, %2, %0;" : "+l"(d) : "l"(a), "l"(b));
}

__global__ void prep_w(const float* __restrict__ W1, const float* __restrict__ W0) {
    const int j = threadIdx.x;
    if (blockIdx.x < 32) {
        const int k4 = blockIdx.x;
        ulonglong2 v;
        v.x = pack2(W1[(4 * k4 + 0) * 128 + j], W1[(4 * k4 + 1) * 128 + j]);
        v.y = pack2(W1[(4 * k4 + 2) * 128 + j], W1[(4 * k4 + 3) * 128 + j]);
        g_W1q[k4 * 128 + j] = v;
    } else {
        const int k4 = blockIdx.x - 32;
        ulonglong2 v;
        v.x = pack2(W0[(4 * k4 + 0) * 128 + j], W0[(4 * k4 + 1) * 128 + j]);
        v.y = pack2(W0[(4 * k4 + 2) * 128 + j], W0[(4 * k4 + 3) * 128 + j]);
        g_W0q[k4 * 128 + j] = v;
    }
}

// ================= Kernel A: gather, 2 warps per row =================
__global__ void __launch_bounds__(256, 5) sage_gather(
    const int*   __restrict__ neigh0,
    const int*   __restrict__ neigh1,
    const float* __restrict__ embed)
{
    __shared__ int sn[8][136];                  // per-warp: 125 n1 ids + 5 n0 ids
    __shared__ __align__(16) float part1[8][64];
    __shared__ __align__(16) float part0[8][64];

    const int t    = threadIdx.x;
    const int w    = t >> 5;                    // warp 0..7
    const int lane = t & 31;
    const int rl   = w >> 1;                    // row-local 0..3
    const int wk   = w & 1;                     // warp-within-row 0/1
    const int row  = blockIdx.x * RPB_A + rl;
    const float4* eb = (const float4*)embed;

    // ---- stage this warp's id half (warp-private) ----
    for (int i = lane; i < 125; i += 32)
        sn[w][i] = __ldg(neigh1 + (size_t)row * 250 + wk * 125 + i);
    if (lane < 5)
        sn[w][128 + lane] = __ldg(neigh0 + row * N0_ + wk * 5 + lane);
    __syncwarp();

    const int c4 = lane & 15;                   // float4 column slot
    const int hh = lane >> 4;                   // id-parity half

    // ---- sum 125 neigh1 embeds (hh: 63/62 ids) ----
    float4 a1 = make_float4(0.f, 0.f, 0.f, 0.f);
    #pragma unroll 5
    for (int i = hh; i < 125; i += 2) {
        const float4 v = __ldg(eb + (size_t)sn[w][i] * 16 + c4);
        a1.x += v.x; a1.y += v.y; a1.z += v.z; a1.w += v.w;
    }
    // ---- sum 5 neigh0 embeds (hh: 3/2 ids) ----
    float4 a0 = make_float4(0.f, 0.f, 0.f, 0.f);
    #pragma unroll
    for (int i = hh; i < 5; i += 2) {
        const float4 v = __ldg(eb + (size_t)sn[w][128 + i] * 16 + c4);
        a0.x += v.x; a0.y += v.y; a0.z += v.z; a0.w += v.w;
    }

    // ---- combine halves within warp ----
    a1.x += __shfl_xor_sync(0xffffffffu, a1.x, 16);
    a1.y += __shfl_xor_sync(0xffffffffu, a1.y, 16);
    a1.z += __shfl_xor_sync(0xffffffffu, a1.z, 16);
    a1.w += __shfl_xor_sync(0xffffffffu, a1.w, 16);
    a0.x += __shfl_xor_sync(0xffffffffu, a0.x, 16);
    a0.y += __shfl_xor_sync(0xffffffffu, a0.y, 16);
    a0.z += __shfl_xor_sync(0xffffffffu, a0.z, 16);
    a0.w += __shfl_xor_sync(0xffffffffu, a0.w, 16);
    if (hh == 0) {
        *(float4*)&part1[w][4 * c4] = a1;
        *(float4*)&part0[w][4 * c4] = a0;
    }
    __syncthreads();

    // ---- combine warp pair + scale + write xbar (256 cells = 4 rows x 64 c) ----
    {
        const int r = t >> 6, c = t & 63;       // r 0..3, c 0..63
        const float s1 = part1[2 * r][c] + part1[2 * r + 1][c];
        const float s0 = part0[2 * r][c] + part0[2 * r + 1][c];
        float* xr = g_xbar + (size_t)(blockIdx.x * RPB_A + r) * 128;
        xr[c]      = s0 * (1.f / 10.f);
        xr[64 + c] = s1 * (1.f / 250.f);
    }
}

// ================= Kernel B: fc1 + fc0 + sigmoid =================
__global__ void __launch_bounds__(256, 4) sage_fc(
    const int*   __restrict__ inputs,
    const float* __restrict__ embed,
    const float* __restrict__ b0,
    float*       __restrict__ out)
{
    __shared__ __align__(16) float xbar[GB][128];
    __shared__ __align__(16) float xb[GB][192];      // [e_v | agg0]

    const int t  = threadIdx.x;
    const int bb = blockIdx.x * GB;
    const float4* eb = (const float4*)embed;

    // load xbar tile (8 x 128 floats = 256 float4), L2-hot
    {
        const int r = t >> 5, q = t & 31;
        *(float4*)&xbar[r][4 * q] =
            *(const float4*)(g_xbar + (size_t)(bb + r) * 128 + 4 * q);
    }
    // e_v gathers (8 rows x 16 float4)
    if (t < GB * 16) {
        const int r = t >> 4, c4 = t & 15;
        *(float4*)&xb[r][4 * c4] =
            __ldg(eb + (size_t)__ldg(inputs + bb + r) * 16 + c4);
    }
    __syncthreads();

    const int j  = t & 127;
    const int h2 = t >> 7;                       // rows h2*4 .. h2*4+3

    // ---- fc1: agg0[r] = xbar[r] @ W1 ----
    {
        unsigned long long acc[4] = {0ull, 0ull, 0ull, 0ull};
        #pragma unroll 4
        for (int k4 = 0; k4 < 32; k4++) {
            const ulonglong2 wv = g_W1q[k4 * 128 + j];
            #pragma unroll
            for (int r = 0; r < 4; r++) {
                const ulonglong2 xv = *(const ulonglong2*)&xbar[h2 * 4 + r][4 * k4];
                ffma2(acc[r], xv.x, wv.x);
                ffma2(acc[r], xv.y, wv.y);
            }
        }
        #pragma unroll
        for (int r = 0; r < 4; r++) {
            float a, b; unpack2(acc[r], a, b);
            xb[h2 * 4 + r][64 + j] = a + b;
        }
    }
    __syncthreads();

    // ---- fc0 + sigmoid ----
    {
        unsigned long long acc[4] = {0ull, 0ull, 0ull, 0ull};
        #pragma unroll 4
        for (int k4 = 0; k4 < 48; k4++) {
            const ulonglong2 wv = g_W0q[k4 * 128 + j];
            #pragma unroll
            for (int r = 0; r < 4; r++) {
                const ulonglong2 xv = *(const ulonglong2*)&xb[h2 * 4 + r][4 * k4];
                ffma2(acc[r], xv.x, wv.x);
                ffma2(acc[r], xv.y, wv.y);
            }
        }
        const float bj = __ldg(b0 + j);
        #pragma unroll
        for (int r = 0; r < 4; r++) {
            float a, b; unpack2(acc[r], a, b);
            const float hv = a + b + bj;
            out[(size_t)(bb + h2 * 4 + r) * 128 + j] = 1.f / (1.f + __expf(-hv));
        }
    }
}

extern "C" void kernel_launch(void* const* d_in, const int* in_sizes, int n_in,
                              void* d_out, int out_size)
{
    // Bind inputs by element count (all distinct):
    //   inputs 4096 | neigh0 40960 | neigh1 1024000 | embed 64000064
    //   W1 16384 | W0 24576 | b0 128
    const int *inputs = nullptr, *neigh0 = nullptr, *neigh1 = nullptr;
    const float *embed = nullptr, *W1 = nullptr, *W0 = nullptr, *b0 = nullptr;
    for (int i = 0; i < n_in; i++) {
        switch (in_sizes[i]) {
            case 4096:     inputs = (const int*)  d_in[i]; break;
            case 40960:    neigh0 = (const int*)  d_in[i]; break;
            case 1024000:  neigh1 = (const int*)  d_in[i]; break;
            case 64000064: embed  = (const float*)d_in[i]; break;
            case 16384:    W1     = (const float*)d_in[i]; break;
            case 24576:    W0     = (const float*)d_in[i]; break;
            case 128:      b0     = (const float*)d_in[i]; break;
        }
    }

    prep_w<<<80, 128>>>(W1, W0);
    sage_gather<<<NBLK_A, 256>>>(neigh0, neigh1, embed);
    sage_fc<<<NBLK_B, 256>>>(inputs, embed, b0, (float*)d_out);
}

// round 14
// speedup vs baseline: 1.0684x; 1.0379x over previous
#include <cuda_runtime.h>
#include <cuda_bf16.h>

// GraphSAGE inference — single-launch, role-specialized blocks with flag overlap.
//   agg0[b] = (mean_n [e_n | mean_nn e_nn]) @ W1  (fc1 linear => commutes w/ mean)
// bids [0,1024): gather (4 rows, 2 warps/row) -> g_xbar + ready flag
// bids [1024,1064): weight pre-pack -> monotone counter (idempotent per replay)
// bids [1064,1576): fc1+fc0+sigmoid, spin-waits flags, overlaps the gather.
// Shapes fixed: B=4096, N0=10, N1=25, D=64, H=128.

#define B_     4096
#define N0_    10
#define N1_    25
#define D_     64
#define RPB_A  4                   // rows per gather block
#define GB     8                   // rows per fc block
#define NGB    (B_ / RPB_A)        // 1024 gather blocks
#define NPB    40                  // prep blocks (10240 elems / 256)
#define NFB    (B_ / GB)           // 512 fc blocks
#define NBLK   (NGB + NPB + NFB)   // 1576

__device__ float g_xbar[(size_t)B_ * 128];    // [sum(e_n)/10 | sum(e_nn)/250], 2MB
__device__ int   g_rdy[NGB];                  // zero-init; set by gather, reset by fc
__device__ int   g_prep_done;                 // monotone counter (never reset)

// Weights packed (k4, j) as ulonglong2 of packed-f32x2 K values.
__device__ ulonglong2 g_W1q[32 * 128];   // K=128
__device__ ulonglong2 g_W0q[48 * 128];   // K=192

// ---- packed-fp32 helpers (f32x2 only via PTX) ----
__device__ __forceinline__ unsigned long long pack2(float a, float b) {
    unsigned long long r;
    asm("mov.b64 %0, {%1, %2};" : "=l"(r) : "f"(a), "f"(b));
    return r;
}
__device__ __forceinline__ void unpack2(unsigned long long v, float& a, float& b) {
    asm("mov.b64 {%0, %1}, %2;" : "=f"(a), "=f"(b) : "l"(v));
}
__device__ __forceinline__ void ffma2(unsigned long long& d,
                                      unsigned long long a, unsigned long long b) {
    asm("fma.rn.f32x2 %0, %1, %2, %0;" : "+l"(d) : "l"(a), "l"(b));
}

__global__ void __launch_bounds__(256, 4) sage_mega(
    const int*   __restrict__ inputs,
    const int*   __restrict__ neigh0,
    const int*   __restrict__ neigh1,
    const float* __restrict__ embed,
    const float* __restrict__ W1,
    const float* __restrict__ W0,
    const float* __restrict__ b0,
    float*       __restrict__ out)
{
    __shared__ int sn[8][136];
    __shared__ __align__(16) float part1[8][64];
    __shared__ __align__(16) float part0[8][64];
    __shared__ __align__(16) float xbar_s[GB][128];
    __shared__ __align__(16) float xb[GB][192];

    const int bid = blockIdx.x;
    const int t   = threadIdx.x;

    if (bid < NGB) {
        // ================= GATHER block: 4 rows, 2 warps/row =================
        const int w    = t >> 5;
        const int lane = t & 31;
        const int rl   = w >> 1;
        const int wk   = w & 1;
        const int row  = bid * RPB_A + rl;
        const float4* eb = (const float4*)embed;

        for (int i = lane; i < 125; i += 32)
            sn[w][i] = __ldg(neigh1 + (size_t)row * 250 + wk * 125 + i);
        if (lane < 5)
            sn[w][128 + lane] = __ldg(neigh0 + row * N0_ + wk * 5 + lane);
        __syncwarp();

        const int c4 = lane & 15;
        const int hh = lane >> 4;

        float4 a1 = make_float4(0.f, 0.f, 0.f, 0.f);
        #pragma unroll 5
        for (int i = hh; i < 125; i += 2) {
            const float4 v = __ldg(eb + (size_t)sn[w][i] * 16 + c4);
            a1.x += v.x; a1.y += v.y; a1.z += v.z; a1.w += v.w;
        }
        float4 a0 = make_float4(0.f, 0.f, 0.f, 0.f);
        #pragma unroll
        for (int i = hh; i < 5; i += 2) {
            const float4 v = __ldg(eb + (size_t)sn[w][128 + i] * 16 + c4);
            a0.x += v.x; a0.y += v.y; a0.z += v.z; a0.w += v.w;
        }
        a1.x += __shfl_xor_sync(0xffffffffu, a1.x, 16);
        a1.y += __shfl_xor_sync(0xffffffffu, a1.y, 16);
        a1.z += __shfl_xor_sync(0xffffffffu, a1.z, 16);
        a1.w += __shfl_xor_sync(0xffffffffu, a1.w, 16);
        a0.x += __shfl_xor_sync(0xffffffffu, a0.x, 16);
        a0.y += __shfl_xor_sync(0xffffffffu, a0.y, 16);
        a0.z += __shfl_xor_sync(0xffffffffu, a0.z, 16);
        a0.w += __shfl_xor_sync(0xffffffffu, a0.w, 16);
        if (hh == 0) {
            *(float4*)&part1[w][4 * c4] = a1;
            *(float4*)&part0[w][4 * c4] = a0;
        }
        __syncthreads();

        {
            const int r = t >> 6, c = t & 63;
            const float s1 = part1[2 * r][c] + part1[2 * r + 1][c];
            const float s0 = part0[2 * r][c] + part0[2 * r + 1][c];
            float* xr = g_xbar + (size_t)(bid * RPB_A + r) * 128;
            xr[c]      = s0 * (1.f / 10.f);
            xr[64 + c] = s1 * (1.f / 250.f);
        }
        __syncthreads();
        if (t == 0) {
            __threadfence();
            ((volatile int*)g_rdy)[bid] = 1;
        }
    } else if (bid < NGB + NPB) {
        // ================= PREP block: pack 256 weight records =================
        const int g = (bid - NGB) * 256 + t;      // 0..10239
        if (g < 4096) {
            const int k4 = g >> 7, j = g & 127;
            ulonglong2 v;
            v.x = pack2(W1[(4 * k4 + 0) * 128 + j], W1[(4 * k4 + 1) * 128 + j]);
            v.y = pack2(W1[(4 * k4 + 2) * 128 + j], W1[(4 * k4 + 3) * 128 + j]);
            g_W1q[k4 * 128 + j] = v;
        } else {
            const int h = g - 4096;               // 0..6143
            const int k4 = h >> 7, j = h & 127;
            ulonglong2 v;
            v.x = pack2(W0[(4 * k4 + 0) * 128 + j], W0[(4 * k4 + 1) * 128 + j]);
            v.y = pack2(W0[(4 * k4 + 2) * 128 + j], W0[(4 * k4 + 3) * 128 + j]);
            g_W0q[k4 * 128 + j] = v;
        }
        __syncthreads();
        if (t == 0) {
            __threadfence();
            atomicAdd(&g_prep_done, 1);           // monotone across replays
        }
    } else {
        // ================= FC block: 8 rows, waits on flags =================
        const int fb = bid - (NGB + NPB);
        const int bb = fb * GB;
        const float4* eb = (const float4*)embed;

        if (t == 0) {
            volatile int* rdy = (volatile int*)g_rdy;
            while (rdy[2 * fb] == 0 || rdy[2 * fb + 1] == 0 ||
                   ((volatile int*)&g_prep_done)[0] < NPB) {
                __nanosleep(64);
            }
            __threadfence();
        }
        __syncthreads();

        // load xbar tile (L2-resident; __ldcg to bypass L1)
        {
            const int r = t >> 5, q = t & 31;
            *(float4*)&xbar_s[r][4 * q] =
                __ldcg((const float4*)(g_xbar + (size_t)(bb + r) * 128 + 4 * q));
        }
        if (t < GB * 16) {
            const int r = t >> 4, c4 = t & 15;
            *(float4*)&xb[r][4 * c4] =
                __ldg(eb + (size_t)__ldg(inputs + bb + r) * 16 + c4);
        }
        __syncthreads();
        if (t == 0) {    // restore zero-invariant for next replay
            ((volatile int*)g_rdy)[2 * fb]     = 0;
            ((volatile int*)g_rdy)[2 * fb + 1] = 0;
        }

        const int j  = t & 127;
        const int h2 = t >> 7;

        // ---- fc1: agg0[r] = xbar[r] @ W1 ----
        {
            unsigned long long acc[4] = {0ull, 0ull, 0ull, 0ull};
            #pragma unroll 4
            for (int k4 = 0; k4 < 32; k4++) {
                const ulonglong2 wv = g_W1q[k4 * 128 + j];
                #pragma unroll
                for (int r = 0; r < 4; r++) {
                    const ulonglong2 xv = *(const ulonglong2*)&xbar_s[h2 * 4 + r][4 * k4];
                    ffma2(acc[r], xv.x, wv.x);
                    ffma2(acc[r], xv.y, wv.y);
                }
            }
            #pragma unroll
            for (int r = 0; r < 4; r++) {
                float a, b; unpack2(acc[r], a, b);
                xb[h2 * 4 + r][64 + j] = a + b;
            }
        }
        __syncthreads();

        // ---- fc0 + sigmoid ----
        {
            unsigned long long acc[4] = {0ull, 0ull, 0ull, 0ull};
            #pragma unroll 4
            for (int k4 = 0; k4 < 48; k4++) {
                const ulonglong2 wv = g_W0q[k4 * 128 + j];
                #pragma unroll
                for (int r = 0; r < 4; r++) {
                    const ulonglong2 xv = *(const ulonglong2*)&xb[h2 * 4 + r][4 * k4];
                    ffma2(acc[r], xv.x, wv.x);
                    ffma2(acc[r], xv.y, wv.y);
                }
            }
            const float bj = __ldg(b0 + j);
            #pragma unroll
            for (int r = 0; r < 4; r++) {
                float a, b; unpack2(acc[r], a, b);
                const float hv = a + b + bj;
                out[(size_t)(bb + h2 * 4 + r) * 128 + j] = 1.f / (1.f + __expf(-hv));
            }
        }
    }
}

extern "C" void kernel_launch(void* const* d_in, const int* in_sizes, int n_in,
                              void* d_out, int out_size)
{
    // Bind inputs by element count (all distinct):
    //   inputs 4096 | neigh0 40960 | neigh1 1024000 | embed 64000064
    //   W1 16384 | W0 24576 | b0 128
    const int *inputs = nullptr, *neigh0 = nullptr, *neigh1 = nullptr;
    const float *embed = nullptr, *W1 = nullptr, *W0 = nullptr, *b0 = nullptr;
    for (int i = 0; i < n_in; i++) {
        switch (in_sizes[i]) {
            case 4096:     inputs = (const int*)  d_in[i]; break;
            case 40960:    neigh0 = (const int*)  d_in[i]; break;
            case 1024000:  neigh1 = (const int*)  d_in[i]; break;
            case 64000064: embed  = (const float*)d_in[i]; break;
            case 16384:    W1     = (const float*)d_in[i]; break;
            case 24576:    W0     = (const float*)d_in[i]; break;
            case 128:      b0     = (const float*)d_in[i]; break;
        }
    }

    sage_mega<<<NBLK, 256>>>(inputs, neigh0, neigh1, embed, W1, W0, b0,
                             (float*)d_out);
}